// round 1
// baseline (speedup 1.0000x reference)
#include <cuda_runtime.h>
#include <math.h>

#define NTOK 2048
#define DM 1024
#define HEADS 16
#define DKH 64

// Scratch (no allocs allowed) — head-major projections + concat buffer.
__device__ float g_Q[HEADS * NTOK * DKH];
__device__ float g_K[HEADS * NTOK * DKH];
__device__ float g_V[HEADS * NTOK * DKH];
__device__ float g_C[NTOK * DM];

// ---------------------------------------------------------------------------
// C[M,DM] = A[M,1024] * B[DM,1024]^T + bias   (NT GEMM, both row-major)
// If HEAD_MAJOR: C is written as [head][row][dk] (head = col/64, dk = col%64)
// Tile: BM=128, BN=128, BK=16. 256 threads, 8x8 per thread (4+4 split).
// ---------------------------------------------------------------------------
template <bool HEAD_MAJOR>
__global__ __launch_bounds__(256) void gemm_nt(const float* __restrict__ A,
                                               const float* __restrict__ B,
                                               const float* __restrict__ bias,
                                               float* __restrict__ C) {
    __shared__ float As[16][130];
    __shared__ float Bs[16][130];

    const int tid = threadIdx.x;
    const int tx = tid & 15;
    const int ty = tid >> 4;
    const int bm = blockIdx.y * 128;
    const int bn = blockIdx.x * 128;

    const float* Ab = A + (size_t)bm * DM;
    const float* Bb = B + (size_t)bn * DM;

    float acc[8][8];
#pragma unroll
    for (int i = 0; i < 8; i++)
#pragma unroll
        for (int j = 0; j < 8; j++) acc[i][j] = 0.f;

    for (int kt = 0; kt < DM; kt += 16) {
#pragma unroll
        for (int it = 0; it < 2; it++) {
            int q = tid + it * 256;          // 512 float4 per tile
            int r = q >> 2;                  // 0..127
            int c4 = (q & 3) * 4;            // 0,4,8,12
            float4 va = *(const float4*)(Ab + (size_t)r * DM + kt + c4);
            As[c4 + 0][r] = va.x; As[c4 + 1][r] = va.y;
            As[c4 + 2][r] = va.z; As[c4 + 3][r] = va.w;
            float4 vb = *(const float4*)(Bb + (size_t)r * DM + kt + c4);
            Bs[c4 + 0][r] = vb.x; Bs[c4 + 1][r] = vb.y;
            Bs[c4 + 2][r] = vb.z; Bs[c4 + 3][r] = vb.w;
        }
        __syncthreads();

#pragma unroll
        for (int k = 0; k < 16; k++) {
            float a[8], b[8];
#pragma unroll
            for (int i = 0; i < 4; i++) {
                a[i]     = As[k][ty * 4 + i];
                a[i + 4] = As[k][64 + ty * 4 + i];
                b[i]     = Bs[k][tx * 4 + i];
                b[i + 4] = Bs[k][64 + tx * 4 + i];
            }
#pragma unroll
            for (int i = 0; i < 8; i++)
#pragma unroll
                for (int j = 0; j < 8; j++) acc[i][j] += a[i] * b[j];
        }
        __syncthreads();
    }

#pragma unroll
    for (int i = 0; i < 8; i++) {
        int row = bm + (i >> 2) * 64 + ty * 4 + (i & 3);
#pragma unroll
        for (int j = 0; j < 8; j++) {
            int col = bn + (j >> 2) * 64 + tx * 4 + (j & 3);
            float v = acc[i][j] + bias[col];
            if (HEAD_MAJOR) {
                C[((size_t)(col >> 6) * NTOK + row) * DKH + (col & 63)] = v;
            } else {
                C[(size_t)row * DM + col] = v;
            }
        }
    }
}

// ---------------------------------------------------------------------------
// Flash attention, fp32. One block per (64 query rows, head).
// 256 threads as 16x16; each thread owns 4x4 of S/P and 4x4 of O.
// K smem tile is reused as the P tile. 1/sqrt(64) folded into Q at load.
// ---------------------------------------------------------------------------
#define ATTN_SMEM (3 * 64 * 65 * 4)

__global__ __launch_bounds__(256) void attn_kernel() {
    extern __shared__ float sm[];
    float* Qs  = sm;                 // [64][65]
    float* KPs = sm + 64 * 65;       // [64][65]  K tile, reused as P
    float* Vs  = sm + 2 * 64 * 65;   // [64][65]

    const int h = blockIdx.y;
    const int bm = blockIdx.x * 64;
    const int tid = threadIdx.x;
    const int tx = tid & 15;
    const int ty = tid >> 4;

    const float* Qg = g_Q + ((size_t)h * NTOK + bm) * DKH;
    const float* Kg = g_K + (size_t)h * NTOK * DKH;
    const float* Vg = g_V + (size_t)h * NTOK * DKH;

    // Load Q tile (scaled by 1/8)
    for (int t = tid; t < 64 * 16; t += 256) {
        int r = t >> 4, c4 = (t & 15) * 4;
        float4 v = *(const float4*)(Qg + (size_t)r * DKH + c4);
        float* qp = Qs + r * 65 + c4;
        qp[0] = v.x * 0.125f; qp[1] = v.y * 0.125f;
        qp[2] = v.z * 0.125f; qp[3] = v.w * 0.125f;
    }

    float m[4], l[4], o[4][4];
#pragma unroll
    for (int i = 0; i < 4; i++) {
        m[i] = -1e30f; l[i] = 0.f;
#pragma unroll
        for (int j = 0; j < 4; j++) o[i][j] = 0.f;
    }

    for (int kt = 0; kt < NTOK; kt += 64) {
        __syncthreads();  // prior PV reads of KPs/Vs done (also covers Qs on iter 0)

        for (int t = tid; t < 64 * 16; t += 256) {
            int r = t >> 4, c4 = (t & 15) * 4;
            float4 kv = *(const float4*)(Kg + (size_t)(kt + r) * DKH + c4);
            float* kp = KPs + r * 65 + c4;
            kp[0] = kv.x; kp[1] = kv.y; kp[2] = kv.z; kp[3] = kv.w;
            float4 vv = *(const float4*)(Vg + (size_t)(kt + r) * DKH + c4);
            float* vp = Vs + r * 65 + c4;
            vp[0] = vv.x; vp[1] = vv.y; vp[2] = vv.z; vp[3] = vv.w;
        }
        __syncthreads();

        // S = (Q/8) * K^T  (64x64, 4x4 per thread)
        float s[4][4];
#pragma unroll
        for (int i = 0; i < 4; i++)
#pragma unroll
            for (int j = 0; j < 4; j++) s[i][j] = 0.f;

#pragma unroll 16
        for (int d = 0; d < 64; d++) {
            float a[4], b[4];
#pragma unroll
            for (int i = 0; i < 4; i++) a[i] = Qs[(ty * 4 + i) * 65 + d];
#pragma unroll
            for (int j = 0; j < 4; j++) b[j] = KPs[(tx * 4 + j) * 65 + d];
#pragma unroll
            for (int i = 0; i < 4; i++)
#pragma unroll
                for (int j = 0; j < 4; j++) s[i][j] += a[i] * b[j];
        }

        // Online softmax update (row stats replicated across the 16 tx lanes)
        float p[4][4];
#pragma unroll
        for (int i = 0; i < 4; i++) {
            float mx = s[i][0];
#pragma unroll
            for (int j = 1; j < 4; j++) mx = fmaxf(mx, s[i][j]);
#pragma unroll
            for (int off = 8; off; off >>= 1)
                mx = fmaxf(mx, __shfl_xor_sync(0xffffffffu, mx, off, 16));
            float mnew = fmaxf(m[i], mx);
            float sc = exp2f((m[i] - mnew) * 1.44269504f);
            m[i] = mnew;
            float ls = 0.f;
#pragma unroll
            for (int j = 0; j < 4; j++) {
                p[i][j] = exp2f((s[i][j] - mnew) * 1.44269504f);
                ls += p[i][j];
            }
#pragma unroll
            for (int off = 8; off; off >>= 1)
                ls += __shfl_xor_sync(0xffffffffu, ls, off, 16);
            l[i] = l[i] * sc + ls;
#pragma unroll
            for (int j = 0; j < 4; j++) o[i][j] *= sc;
        }

        __syncthreads();  // everyone done reading K before overwrite with P
#pragma unroll
        for (int i = 0; i < 4; i++)
#pragma unroll
            for (int j = 0; j < 4; j++)
                KPs[(ty * 4 + i) * 65 + tx * 4 + j] = p[i][j];
        __syncthreads();

        // O += P * V
#pragma unroll 16
        for (int jj = 0; jj < 64; jj++) {
            float a[4], b[4];
#pragma unroll
            for (int i = 0; i < 4; i++) a[i] = KPs[(ty * 4 + i) * 65 + jj];
#pragma unroll
            for (int j = 0; j < 4; j++) b[j] = Vs[jj * 65 + tx * 4 + j];
#pragma unroll
            for (int i = 0; i < 4; i++)
#pragma unroll
                for (int j = 0; j < 4; j++) o[i][j] += a[i] * b[j];
        }
    }

    // Normalize and write into concat layout [row][h*64+dk]
#pragma unroll
    for (int i = 0; i < 4; i++) {
        float inv = 1.f / l[i];
#pragma unroll
        for (int j = 0; j < 4; j++) {
            g_C[(size_t)(bm + ty * 4 + i) * DM + h * DKH + tx * 4 + j] =
                o[i][j] * inv;
        }
    }
}

// ---------------------------------------------------------------------------
extern "C" void kernel_launch(void* const* d_in, const int* in_sizes, int n_in,
                              void* d_out, int out_size) {
    const float* q  = (const float*)d_in[0];
    const float* k  = (const float*)d_in[1];
    const float* v  = (const float*)d_in[2];
    const float* Wq = (const float*)d_in[3];
    const float* bq = (const float*)d_in[4];
    const float* Wk = (const float*)d_in[5];
    const float* bk = (const float*)d_in[6];
    const float* Wv = (const float*)d_in[7];
    const float* bv = (const float*)d_in[8];
    const float* Wo = (const float*)d_in[9];
    const float* bo = (const float*)d_in[10];
    float* out = (float*)d_out;

    float *Qp, *Kp, *Vp, *Cp;
    cudaGetSymbolAddress((void**)&Qp, g_Q);
    cudaGetSymbolAddress((void**)&Kp, g_K);
    cudaGetSymbolAddress((void**)&Vp, g_V);
    cudaGetSymbolAddress((void**)&Cp, g_C);

    cudaFuncSetAttribute(attn_kernel,
                         cudaFuncAttributeMaxDynamicSharedMemorySize, ATTN_SMEM);

    dim3 gb(DM / 128, NTOK / 128);  // (8, 16)
    dim3 tb(256);

    gemm_nt<true><<<gb, tb>>>(q, Wq, bq, Qp);
    gemm_nt<true><<<gb, tb>>>(k, Wk, bk, Kp);
    gemm_nt<true><<<gb, tb>>>(v, Wv, bv, Vp);

    attn_kernel<<<dim3(NTOK / 64, HEADS), tb, ATTN_SMEM>>>();

    gemm_nt<false><<<gb, tb>>>(Cp, Wo, bo, out);
}

// round 3
// speedup vs baseline: 3.3824x; 3.3824x over previous
#include <cuda_runtime.h>
#include <cuda_bf16.h>
#include <math.h>
#include <stdint.h>

#define NTOK 2048
#define DM 1024
#define HEADS 16
#define DKH 64
#define LOG2E 1.44269504f

typedef __nv_bfloat16 bf16;
typedef __nv_bfloat162 bf162;

// ---------------------------------------------------------------------------
// Scratch (__device__ globals; no allocs allowed)
// ---------------------------------------------------------------------------
__device__ __align__(128) bf16 g_qh[NTOK * DM], g_ql[NTOK * DM];
__device__ __align__(128) bf16 g_kh[NTOK * DM], g_kl[NTOK * DM];
__device__ __align__(128) bf16 g_vh[NTOK * DM], g_vl[NTOK * DM];
__device__ __align__(128) bf16 g_Wqh[DM * DM], g_Wql[DM * DM];
__device__ __align__(128) bf16 g_Wkh[DM * DM], g_Wkl[DM * DM];
__device__ __align__(128) bf16 g_Wvh[DM * DM], g_Wvl[DM * DM];
__device__ __align__(128) bf16 g_Woh[DM * DM], g_Wol[DM * DM];
// head-major projected Q/K/V, bf16 hi/lo
__device__ __align__(128) bf16 g_Qh[HEADS * NTOK * DKH], g_Ql[HEADS * NTOK * DKH];
__device__ __align__(128) bf16 g_Kh[HEADS * NTOK * DKH], g_Kl[HEADS * NTOK * DKH];
__device__ __align__(128) bf16 g_Vh[HEADS * NTOK * DKH], g_Vl[HEADS * NTOK * DKH];
// attention output (concat layout), bf16 hi/lo
__device__ __align__(128) bf16 g_Ch[NTOK * DM], g_Cl[NTOK * DM];

// ---------------------------------------------------------------------------
// Warp MMA helpers (all base compute_100 features: sm_75/80-era PTX)
// ---------------------------------------------------------------------------
__device__ __forceinline__ uint32_t smem_u32(const void* p) {
    return (uint32_t)__cvta_generic_to_shared(p);
}

__device__ __forceinline__ void mma_bf16(float c[4], const uint32_t a[4],
                                         uint32_t b0, uint32_t b1) {
    asm volatile(
        "mma.sync.aligned.m16n8k16.row.col.f32.bf16.bf16.f32 "
        "{%0,%1,%2,%3}, {%4,%5,%6,%7}, {%8,%9}, {%0,%1,%2,%3};"
        : "+f"(c[0]), "+f"(c[1]), "+f"(c[2]), "+f"(c[3])
        : "r"(a[0]), "r"(a[1]), "r"(a[2]), "r"(a[3]), "r"(b0), "r"(b1));
}

__device__ __forceinline__ void ldmx4(uint32_t r[4], uint32_t addr) {
    asm volatile(
        "ldmatrix.sync.aligned.m8n8.x4.shared.b16 {%0,%1,%2,%3}, [%4];"
        : "=r"(r[0]), "=r"(r[1]), "=r"(r[2]), "=r"(r[3]) : "r"(addr));
}
__device__ __forceinline__ void ldmx4t(uint32_t r[4], uint32_t addr) {
    asm volatile(
        "ldmatrix.sync.aligned.m8n8.x4.trans.shared.b16 {%0,%1,%2,%3}, [%4];"
        : "=r"(r[0]), "=r"(r[1]), "=r"(r[2]), "=r"(r[3]) : "r"(addr));
}

// Tile format: [rows][64 bf16], row pitch 128B, 16B chunk c swizzled: c ^ (r&7)
__device__ __forceinline__ uint32_t taddr(uint32_t base, int r, int c) {
    return base + r * 128 + (((uint32_t)(c ^ (r & 7))) << 4);
}

// A fragment (m16 x k16) at (row0, kchunk0=2s). a0=TL a1=BL a2=TR a3=BR.
__device__ __forceinline__ void ldfragA(uint32_t f[4], uint32_t tb, int row0,
                                        int c0, int lane) {
    int grp = lane >> 3, lr = lane & 7;
    int r = row0 + (grp & 1) * 8 + lr;
    int c = c0 + (grp >> 1);
    ldmx4(f, taddr(tb, r, c));
}
// B fragment pair (two n8 tiles, k16) from row-major Brm[n][k] (NT layout).
// regs: {b0 tile0, b1 tile0, b0 tile1, b1 tile1}
__device__ __forceinline__ void ldfragB(uint32_t f[4], uint32_t tb, int n0,
                                        int c0, int lane) {
    int grp = lane >> 3, lr = lane & 7;
    int r = n0 + (grp >> 1) * 8 + lr;
    int c = c0 + (grp & 1);
    ldmx4(f, taddr(tb, r, c));
}
// V fragment pair (two n8 d-tiles, k16) from V[kv][d] via trans ldmatrix.
__device__ __forceinline__ void ldfragV(uint32_t f[4], uint32_t tb, int k0,
                                        int c0, int lane) {
    int grp = lane >> 3, lr = lane & 7;
    int r = k0 + (grp & 1) * 8 + lr;
    int c = c0 + (grp >> 1);
    ldmx4t(f, taddr(tb, r, c));
}

// async-copy one [ROWS x 64 bf16] tile into swizzled smem (256 threads)
template <int ROWS>
__device__ __forceinline__ void load_tile(uint32_t sbase, const bf16* g,
                                          int pitch, int tid) {
#pragma unroll
    for (int i = 0; i < ROWS * 8 / 256; i++) {
        int idx = i * 256 + tid;
        int r = idx >> 3, c = idx & 7;
        uint32_t dst = taddr(sbase, r, c);
        const void* src = g + (size_t)r * pitch + c * 8;
        asm volatile("cp.async.cg.shared.global [%0], [%1], 16;"
                     :: "r"(dst), "l"(src) : "memory");
    }
}
__device__ __forceinline__ void cp_commit() {
    asm volatile("cp.async.commit_group;" ::: "memory");
}

// ---------------------------------------------------------------------------
// fp32 -> (bf16 hi, bf16 lo) split
// ---------------------------------------------------------------------------
__global__ __launch_bounds__(256) void cvt_split(const float* __restrict__ x,
                                                 bf16* __restrict__ hi,
                                                 bf16* __restrict__ lo, int n4) {
    int i = blockIdx.x * 256 + threadIdx.x;
    if (i >= n4) return;
    float4 v = ((const float4*)x)[i];
    bf16 h0 = __float2bfloat16_rn(v.x);
    bf16 h1 = __float2bfloat16_rn(v.y);
    bf16 h2 = __float2bfloat16_rn(v.z);
    bf16 h3 = __float2bfloat16_rn(v.w);
    bf162* hp = (bf162*)(hi + i * 4);
    hp[0] = bf162(h0, h1);
    hp[1] = bf162(h2, h3);
    bf162* lp = (bf162*)(lo + i * 4);
    lp[0] = bf162(__float2bfloat16_rn(v.x - __bfloat162float(h0)),
                  __float2bfloat16_rn(v.y - __bfloat162float(h1)));
    lp[1] = bf162(__float2bfloat16_rn(v.z - __bfloat162float(h2)),
                  __float2bfloat16_rn(v.w - __bfloat162float(h3)));
}

// ---------------------------------------------------------------------------
// bf16x3 NT-GEMM on mma.sync: C[M x 1024] = A[M x 1024] * B[1024 x 1024]^T + bias
// CTA tile 128x128, warp tile 64x32 (2x4 warps), k staged 64, double buffer.
// MODE 0: fp32 row-major out.  MODE 1: bf16 hi/lo split, head-major, * scale.
// ---------------------------------------------------------------------------
#define GEMM_SMEM (2 * 65536)

template <int MODE>
__global__ __launch_bounds__(256) void gemm_mma(
    const bf16* __restrict__ Ah, const bf16* __restrict__ Al,
    const bf16* __restrict__ Bh, const bf16* __restrict__ Bl,
    const float* __restrict__ bias, float* __restrict__ outF,
    bf16* __restrict__ oH, bf16* __restrict__ oL, float scale) {
    extern __shared__ char smem[];
    const uint32_t sbase = smem_u32(smem);
    const int tid = threadIdx.x;
    const int lane = tid & 31;
    const int w = tid >> 5;
    const int wm = w >> 2, wn = w & 3;
    const int bm = blockIdx.y * 128, bn = blockIdx.x * 128;

    auto load_stage = [&](int kt, int b) {
        uint32_t s0 = sbase + b * 65536;
        load_tile<128>(s0 +     0, Ah + (size_t)bm * DM + kt, DM, tid);
        load_tile<128>(s0 + 16384, Al + (size_t)bm * DM + kt, DM, tid);
        load_tile<128>(s0 + 32768, Bh + (size_t)bn * DM + kt, DM, tid);
        load_tile<128>(s0 + 49152, Bl + (size_t)bn * DM + kt, DM, tid);
        cp_commit();
    };

    float c[4][4][4];
#pragma unroll
    for (int i = 0; i < 4; i++)
#pragma unroll
        for (int j = 0; j < 4; j++)
#pragma unroll
            for (int k = 0; k < 4; k++) c[i][j][k] = 0.f;

    load_stage(0, 0);
    load_stage(64, 1);

    for (int it = 0; it < 16; it++) {
        if (it < 15) asm volatile("cp.async.wait_group 1;" ::: "memory");
        else         asm volatile("cp.async.wait_group 0;" ::: "memory");
        __syncthreads();

        uint32_t s0 = sbase + (it & 1) * 65536;
#pragma unroll
        for (int s = 0; s < 4; s++) {
            uint32_t aH[4][4], aL[4][4], bH[2][4], bL[2][4];
#pragma unroll
            for (int mt = 0; mt < 4; mt++) {
                ldfragA(aH[mt], s0,          wm * 64 + mt * 16, 2 * s, lane);
                ldfragA(aL[mt], s0 + 16384,  wm * 64 + mt * 16, 2 * s, lane);
            }
#pragma unroll
            for (int np = 0; np < 2; np++) {
                ldfragB(bH[np], s0 + 32768, wn * 32 + np * 16, 2 * s, lane);
                ldfragB(bL[np], s0 + 49152, wn * 32 + np * 16, 2 * s, lane);
            }
#pragma unroll
            for (int mt = 0; mt < 4; mt++)
#pragma unroll
                for (int np = 0; np < 2; np++)
#pragma unroll
                    for (int hf = 0; hf < 2; hf++) {
                        int nt = np * 2 + hf;
                        mma_bf16(c[mt][nt], aH[mt], bH[np][2 * hf], bH[np][2 * hf + 1]);
                        mma_bf16(c[mt][nt], aH[mt], bL[np][2 * hf], bL[np][2 * hf + 1]);
                        mma_bf16(c[mt][nt], aL[mt], bH[np][2 * hf], bH[np][2 * hf + 1]);
                    }
        }
        __syncthreads();
        if (it + 2 < 16) load_stage((it + 2) * 64, it & 1);
    }

    // Epilogue
#pragma unroll
    for (int mt = 0; mt < 4; mt++)
#pragma unroll
        for (int nt = 0; nt < 4; nt++) {
            int r0 = bm + wm * 64 + mt * 16 + (lane >> 2);
            int col = bn + wn * 32 + nt * 8 + 2 * (lane & 3);
            float b0 = bias[col], b1 = bias[col + 1];
#pragma unroll
            for (int h2 = 0; h2 < 2; h2++) {
                int r = r0 + h2 * 8;
                float x0 = (c[mt][nt][2 * h2]     + b0) * scale;
                float x1 = (c[mt][nt][2 * h2 + 1] + b1) * scale;
                if (MODE == 0) {
                    float2 v = {x0, x1};
                    *(float2*)(outF + (size_t)r * DM + col) = v;
                } else {
                    bf16 h0 = __float2bfloat16_rn(x0);
                    bf16 h1 = __float2bfloat16_rn(x1);
                    size_t off = ((size_t)(col >> 6) * NTOK + r) * DKH + (col & 63);
                    *(bf162*)(oH + off) = bf162(h0, h1);
                    *(bf162*)(oL + off) =
                        bf162(__float2bfloat16_rn(x0 - __bfloat162float(h0)),
                              __float2bfloat16_rn(x1 - __bfloat162float(h1)));
                }
            }
        }
}

// ---------------------------------------------------------------------------
// Flash attention on mma.sync bf16x3.
// Block: (128 q rows, 1 head). 8 warps, each owns 16 rows x full 64-kv tile.
// ---------------------------------------------------------------------------
#define ATTN_SMEM (32768 + 2 * 32768)

__global__ __launch_bounds__(256) void attn_mma() {
    extern __shared__ char smem[];
    const uint32_t sbase = smem_u32(smem);
    const int h = blockIdx.y;
    const int row0 = blockIdx.x * 128;
    const int tid = threadIdx.x;
    const int lane = tid & 31;
    const int w = tid >> 5;

    const size_t hbase = (size_t)h * NTOK * DKH;

    // Q tiles (hi @0, lo @16K)
    load_tile<128>(sbase,         g_Qh + hbase + (size_t)row0 * DKH, DKH, tid);
    load_tile<128>(sbase + 16384, g_Ql + hbase + (size_t)row0 * DKH, DKH, tid);
    cp_commit();

    auto kvb = [&](int b) { return sbase + 32768 + b * 32768; };
    auto load_kv = [&](int t, int b) {
        size_t off = hbase + (size_t)t * 64 * DKH;
        uint32_t s0 = kvb(b);
        load_tile<64>(s0 +     0, g_Kh + off, DKH, tid);
        load_tile<64>(s0 +  8192, g_Kl + off, DKH, tid);
        load_tile<64>(s0 + 16384, g_Vh + off, DKH, tid);
        load_tile<64>(s0 + 24576, g_Vl + off, DKH, tid);
        cp_commit();
    };

    load_kv(0, 0);
    load_kv(1, 1);

    // Q fragments (after Q group done: 2 kv groups may remain outstanding)
    asm volatile("cp.async.wait_group 2;" ::: "memory");
    __syncthreads();
    uint32_t qh[4][4], ql[4][4];
#pragma unroll
    for (int s = 0; s < 4; s++) {
        ldfragA(qh[s], sbase,         w * 16, 2 * s, lane);
        ldfragA(ql[s], sbase + 16384, w * 16, 2 * s, lane);
    }

    float m2[2] = {-1e30f, -1e30f}, l2[2] = {0.f, 0.f};
    float o[8][4];
#pragma unroll
    for (int i = 0; i < 8; i++)
#pragma unroll
        for (int j = 0; j < 4; j++) o[i][j] = 0.f;

    for (int i = 0; i < NTOK / 64; i++) {
        const int b = i & 1;
        if (i < NTOK / 64 - 1) asm volatile("cp.async.wait_group 1;" ::: "memory");
        else                   asm volatile("cp.async.wait_group 0;" ::: "memory");
        __syncthreads();
        const uint32_t s0 = kvb(b);

        // S = Q K^T (already includes 1/sqrt(dk) folded into Q)
        float sc[8][4];
#pragma unroll
        for (int t = 0; t < 8; t++)
#pragma unroll
            for (int j = 0; j < 4; j++) sc[t][j] = 0.f;

#pragma unroll
        for (int s = 0; s < 4; s++) {
            uint32_t kh[4][4], kl[4][4];
#pragma unroll
            for (int np = 0; np < 4; np++) {
                ldfragB(kh[np], s0,        np * 16, 2 * s, lane);
                ldfragB(kl[np], s0 + 8192, np * 16, 2 * s, lane);
            }
#pragma unroll
            for (int np = 0; np < 4; np++)
#pragma unroll
                for (int hf = 0; hf < 2; hf++) {
                    int nt = np * 2 + hf;
                    mma_bf16(sc[nt], qh[s], kh[np][2 * hf], kh[np][2 * hf + 1]);
                    mma_bf16(sc[nt], qh[s], kl[np][2 * hf], kl[np][2 * hf + 1]);
                    mma_bf16(sc[nt], ql[s], kh[np][2 * hf], kh[np][2 * hf + 1]);
                }
        }

        // online softmax per row-half (each thread owns rows lane/4 and lane/4+8)
#pragma unroll
        for (int h2 = 0; h2 < 2; h2++) {
            float mx = -1e30f;
#pragma unroll
            for (int nt = 0; nt < 8; nt++)
                mx = fmaxf(mx, fmaxf(sc[nt][2 * h2], sc[nt][2 * h2 + 1]));
            mx = fmaxf(mx, __shfl_xor_sync(0xffffffffu, mx, 1));
            mx = fmaxf(mx, __shfl_xor_sync(0xffffffffu, mx, 2));
            float mnew = fmaxf(m2[h2], mx);
            float corr = exp2f((m2[h2] - mnew) * LOG2E);
            m2[h2] = mnew;
            float ls = 0.f;
#pragma unroll
            for (int nt = 0; nt < 8; nt++) {
                float p0 = exp2f((sc[nt][2 * h2]     - mnew) * LOG2E);
                float p1 = exp2f((sc[nt][2 * h2 + 1] - mnew) * LOG2E);
                sc[nt][2 * h2] = p0;
                sc[nt][2 * h2 + 1] = p1;
                ls += p0 + p1;
            }
            ls += __shfl_xor_sync(0xffffffffu, ls, 1);
            ls += __shfl_xor_sync(0xffffffffu, ls, 2);
            l2[h2] = l2[h2] * corr + ls;
#pragma unroll
            for (int nt = 0; nt < 8; nt++) {
                o[nt][2 * h2] *= corr;
                o[nt][2 * h2 + 1] *= corr;
            }
        }

        // P -> hi/lo A-fragments (C layout == A layout after bf16x2 pack)
        uint32_t pah[4][4], pal[4][4];
#pragma unroll
        for (int s = 0; s < 4; s++)
#pragma unroll
            for (int j = 0; j < 4; j++) {
                int t = 2 * s + (j >> 1);
                float v0 = sc[t][(j & 1) * 2];
                float v1 = sc[t][(j & 1) * 2 + 1];
                bf16 h0 = __float2bfloat16_rn(v0);
                bf16 h1 = __float2bfloat16_rn(v1);
                bf162 ph = bf162(h0, h1);
                bf162 pl = bf162(__float2bfloat16_rn(v0 - __bfloat162float(h0)),
                                 __float2bfloat16_rn(v1 - __bfloat162float(h1)));
                pah[s][j] = *(uint32_t*)&ph;
                pal[s][j] = *(uint32_t*)&pl;
            }

        // O += P V
#pragma unroll
        for (int s = 0; s < 4; s++) {
            uint32_t vh[4][4], vl[4][4];
#pragma unroll
            for (int tp = 0; tp < 4; tp++) {
                ldfragV(vh[tp], s0 + 16384, s * 16, 2 * tp, lane);
                ldfragV(vl[tp], s0 + 24576, s * 16, 2 * tp, lane);
            }
#pragma unroll
            for (int tp = 0; tp < 4; tp++)
#pragma unroll
                for (int hf = 0; hf < 2; hf++) {
                    int nt = tp * 2 + hf;
                    mma_bf16(o[nt], pah[s], vh[tp][2 * hf], vh[tp][2 * hf + 1]);
                    mma_bf16(o[nt], pah[s], vl[tp][2 * hf], vl[tp][2 * hf + 1]);
                    mma_bf16(o[nt], pal[s], vh[tp][2 * hf], vh[tp][2 * hf + 1]);
                }
        }

        __syncthreads();
        if (i + 2 < NTOK / 64) load_kv(i + 2, b);
    }

    // Epilogue: normalize, hi/lo split, write concat layout [row][h*64+col]
#pragma unroll
    for (int h2 = 0; h2 < 2; h2++) {
        float inv = 1.f / l2[h2];
        int r = row0 + w * 16 + h2 * 8 + (lane >> 2);
#pragma unroll
        for (int nt = 0; nt < 8; nt++) {
            int col = nt * 8 + 2 * (lane & 3);
            float x0 = o[nt][2 * h2] * inv;
            float x1 = o[nt][2 * h2 + 1] * inv;
            bf16 h0 = __float2bfloat16_rn(x0);
            bf16 h1 = __float2bfloat16_rn(x1);
            size_t off = (size_t)r * DM + h * DKH + col;
            *(bf162*)(g_Ch + off) = bf162(h0, h1);
            *(bf162*)(g_Cl + off) =
                bf162(__float2bfloat16_rn(x0 - __bfloat162float(h0)),
                      __float2bfloat16_rn(x1 - __bfloat162float(h1)));
        }
    }
}

// ---------------------------------------------------------------------------
extern "C" void kernel_launch(void* const* d_in, const int* in_sizes, int n_in,
                              void* d_out, int out_size) {
    const float* q  = (const float*)d_in[0];
    const float* k  = (const float*)d_in[1];
    const float* v  = (const float*)d_in[2];
    const float* Wq = (const float*)d_in[3];
    const float* bq = (const float*)d_in[4];
    const float* Wk = (const float*)d_in[5];
    const float* bk = (const float*)d_in[6];
    const float* Wv = (const float*)d_in[7];
    const float* bv = (const float*)d_in[8];
    const float* Wo = (const float*)d_in[9];
    const float* bo = (const float*)d_in[10];
    float* out = (float*)d_out;

    bf16 *qh, *ql, *kh, *kl, *vh, *vl;
    bf16 *Wqh, *Wql, *Wkh, *Wkl, *Wvh, *Wvl, *Woh, *Wol;
    bf16 *Qh, *Ql, *Kh, *Kl, *Vh, *Vl, *Ch, *Cl;
    cudaGetSymbolAddress((void**)&qh, g_qh);   cudaGetSymbolAddress((void**)&ql, g_ql);
    cudaGetSymbolAddress((void**)&kh, g_kh);   cudaGetSymbolAddress((void**)&kl, g_kl);
    cudaGetSymbolAddress((void**)&vh, g_vh);   cudaGetSymbolAddress((void**)&vl, g_vl);
    cudaGetSymbolAddress((void**)&Wqh, g_Wqh); cudaGetSymbolAddress((void**)&Wql, g_Wql);
    cudaGetSymbolAddress((void**)&Wkh, g_Wkh); cudaGetSymbolAddress((void**)&Wkl, g_Wkl);
    cudaGetSymbolAddress((void**)&Wvh, g_Wvh); cudaGetSymbolAddress((void**)&Wvl, g_Wvl);
    cudaGetSymbolAddress((void**)&Woh, g_Woh); cudaGetSymbolAddress((void**)&Wol, g_Wol);
    cudaGetSymbolAddress((void**)&Qh, g_Qh);   cudaGetSymbolAddress((void**)&Ql, g_Ql);
    cudaGetSymbolAddress((void**)&Kh, g_Kh);   cudaGetSymbolAddress((void**)&Kl, g_Kl);
    cudaGetSymbolAddress((void**)&Vh, g_Vh);   cudaGetSymbolAddress((void**)&Vl, g_Vl);
    cudaGetSymbolAddress((void**)&Ch, g_Ch);   cudaGetSymbolAddress((void**)&Cl, g_Cl);

    cudaFuncSetAttribute(gemm_mma<0>, cudaFuncAttributeMaxDynamicSharedMemorySize, GEMM_SMEM);
    cudaFuncSetAttribute(gemm_mma<1>, cudaFuncAttributeMaxDynamicSharedMemorySize, GEMM_SMEM);
    cudaFuncSetAttribute(attn_mma, cudaFuncAttributeMaxDynamicSharedMemorySize, ATTN_SMEM);

    const int nQKV4 = NTOK * DM / 4;
    const int nW4 = DM * DM / 4;
    cvt_split<<<(nQKV4 + 255) / 256, 256>>>(q, qh, ql, nQKV4);
    cvt_split<<<(nQKV4 + 255) / 256, 256>>>(k, kh, kl, nQKV4);
    cvt_split<<<(nQKV4 + 255) / 256, 256>>>(v, vh, vl, nQKV4);
    cvt_split<<<(nW4 + 255) / 256, 256>>>(Wq, Wqh, Wql, nW4);
    cvt_split<<<(nW4 + 255) / 256, 256>>>(Wk, Wkh, Wkl, nW4);
    cvt_split<<<(nW4 + 255) / 256, 256>>>(Wv, Wvh, Wvl, nW4);
    cvt_split<<<(nW4 + 255) / 256, 256>>>(Wo, Woh, Wol, nW4);

    dim3 gg(DM / 128, NTOK / 128);  // (8,16)
    gemm_mma<1><<<gg, 256, GEMM_SMEM>>>(qh, ql, Wqh, Wql, bq, nullptr, Qh, Ql, 0.125f);
    gemm_mma<1><<<gg, 256, GEMM_SMEM>>>(kh, kl, Wkh, Wkl, bk, nullptr, Kh, Kl, 1.0f);
    gemm_mma<1><<<gg, 256, GEMM_SMEM>>>(vh, vl, Wvh, Wvl, bv, nullptr, Vh, Vl, 1.0f);

    attn_mma<<<dim3(NTOK / 128, HEADS), 256, ATTN_SMEM>>>();

    gemm_mma<0><<<gg, 256, GEMM_SMEM>>>(Ch, Cl, Woh, Wol, bo, out, nullptr, nullptr, 1.0f);
}

// round 4
// speedup vs baseline: 3.9226x; 1.1597x over previous
#include <cuda_runtime.h>
#include <cuda_bf16.h>
#include <math.h>
#include <stdint.h>

#define NTOK 2048
#define DM 1024
#define HEADS 16
#define DKH 64
#define LOG2E 1.44269504f

typedef __nv_bfloat16 bf16;
typedef __nv_bfloat162 bf162;

// ---------------------------------------------------------------------------
// Scratch (__device__ globals; no allocs allowed)
// ---------------------------------------------------------------------------
__device__ __align__(128) bf16 g_qh[NTOK * DM], g_ql[NTOK * DM];
__device__ __align__(128) bf16 g_kh[NTOK * DM], g_kl[NTOK * DM];
__device__ __align__(128) bf16 g_vh[NTOK * DM], g_vl[NTOK * DM];
__device__ __align__(128) bf16 g_Wqh[DM * DM], g_Wql[DM * DM];
__device__ __align__(128) bf16 g_Wkh[DM * DM], g_Wkl[DM * DM];
__device__ __align__(128) bf16 g_Wvh[DM * DM], g_Wvl[DM * DM];
__device__ __align__(128) bf16 g_Woh[DM * DM], g_Wol[DM * DM];
__device__ __align__(128) bf16 g_Qh[HEADS * NTOK * DKH], g_Ql[HEADS * NTOK * DKH];
__device__ __align__(128) bf16 g_Kh[HEADS * NTOK * DKH], g_Kl[HEADS * NTOK * DKH];
__device__ __align__(128) bf16 g_Vh[HEADS * NTOK * DKH], g_Vl[HEADS * NTOK * DKH];
__device__ __align__(128) bf16 g_Ch[NTOK * DM], g_Cl[NTOK * DM];

// ---------------------------------------------------------------------------
// Warp MMA helpers (base compute_100 features only)
// ---------------------------------------------------------------------------
__device__ __forceinline__ uint32_t smem_u32(const void* p) {
    return (uint32_t)__cvta_generic_to_shared(p);
}

__device__ __forceinline__ void mma_bf16(float c[4], const uint32_t a[4],
                                         uint32_t b0, uint32_t b1) {
    asm volatile(
        "mma.sync.aligned.m16n8k16.row.col.f32.bf16.bf16.f32 "
        "{%0,%1,%2,%3}, {%4,%5,%6,%7}, {%8,%9}, {%0,%1,%2,%3};"
        : "+f"(c[0]), "+f"(c[1]), "+f"(c[2]), "+f"(c[3])
        : "r"(a[0]), "r"(a[1]), "r"(a[2]), "r"(a[3]), "r"(b0), "r"(b1));
}

__device__ __forceinline__ void ldmx4(uint32_t r[4], uint32_t addr) {
    asm volatile(
        "ldmatrix.sync.aligned.m8n8.x4.shared.b16 {%0,%1,%2,%3}, [%4];"
        : "=r"(r[0]), "=r"(r[1]), "=r"(r[2]), "=r"(r[3]) : "r"(addr));
}
__device__ __forceinline__ void ldmx4t(uint32_t r[4], uint32_t addr) {
    asm volatile(
        "ldmatrix.sync.aligned.m8n8.x4.trans.shared.b16 {%0,%1,%2,%3}, [%4];"
        : "=r"(r[0]), "=r"(r[1]), "=r"(r[2]), "=r"(r[3]) : "r"(addr));
}

// Tile format: [rows][64 bf16], row pitch 128B, 16B chunk c swizzled: c ^ (r&7)
__device__ __forceinline__ uint32_t taddr(uint32_t base, int r, int c) {
    return base + r * 128 + (((uint32_t)(c ^ (r & 7))) << 4);
}

__device__ __forceinline__ void ldfragA(uint32_t f[4], uint32_t tb, int row0,
                                        int c0, int lane) {
    int grp = lane >> 3, lr = lane & 7;
    ldmx4(f, taddr(tb, row0 + (grp & 1) * 8 + lr, c0 + (grp >> 1)));
}
__device__ __forceinline__ void ldfragB(uint32_t f[4], uint32_t tb, int n0,
                                        int c0, int lane) {
    int grp = lane >> 3, lr = lane & 7;
    ldmx4(f, taddr(tb, n0 + (grp >> 1) * 8 + lr, c0 + (grp & 1)));
}
__device__ __forceinline__ void ldfragV(uint32_t f[4], uint32_t tb, int k0,
                                        int c0, int lane) {
    int grp = lane >> 3, lr = lane & 7;
    ldmx4t(f, taddr(tb, k0 + (grp & 1) * 8 + lr, c0 + (grp >> 1)));
}

template <int ROWS>
__device__ __forceinline__ void load_tile(uint32_t sbase, const bf16* g,
                                          int pitch, int tid) {
#pragma unroll
    for (int i = 0; i < ROWS * 8 / 256; i++) {
        int idx = i * 256 + tid;
        int r = idx >> 3, c = idx & 7;
        uint32_t dst = taddr(sbase, r, c);
        const void* src = g + (size_t)r * pitch + c * 8;
        asm volatile("cp.async.cg.shared.global [%0], [%1], 16;"
                     :: "r"(dst), "l"(src) : "memory");
    }
}
__device__ __forceinline__ void cp_commit() {
    asm volatile("cp.async.commit_group;" ::: "memory");
}

// ---------------------------------------------------------------------------
// Batched fp32 -> (bf16 hi, bf16 lo) split: 7 jobs, 4 float4 per thread
// ---------------------------------------------------------------------------
struct CvtJobs {
    const float* src[7];
    bf16* hi[7];
    bf16* lo[7];
    int n4[7];
};

__global__ __launch_bounds__(256) void cvt_all(CvtJobs jobs) {
    const int j = blockIdx.y;
    const int n4 = jobs.n4[j];
    const int blk = blockIdx.x * 1024;
    if (blk >= n4) return;
    const int base = blk + threadIdx.x;
    const float4* src = (const float4*)jobs.src[j];

    float4 v[4];
#pragma unroll
    for (int u = 0; u < 4; u++) v[u] = src[base + u * 256];

#pragma unroll
    for (int u = 0; u < 4; u++) {
        int i = base + u * 256;
        bf16 h0 = __float2bfloat16_rn(v[u].x);
        bf16 h1 = __float2bfloat16_rn(v[u].y);
        bf16 h2 = __float2bfloat16_rn(v[u].z);
        bf16 h3 = __float2bfloat16_rn(v[u].w);
        bf162* hp = (bf162*)(jobs.hi[j] + i * 4);
        hp[0] = bf162(h0, h1);
        hp[1] = bf162(h2, h3);
        bf162* lp = (bf162*)(jobs.lo[j] + i * 4);
        lp[0] = bf162(__float2bfloat16_rn(v[u].x - __bfloat162float(h0)),
                      __float2bfloat16_rn(v[u].y - __bfloat162float(h1)));
        lp[1] = bf162(__float2bfloat16_rn(v[u].z - __bfloat162float(h2)),
                      __float2bfloat16_rn(v[u].w - __bfloat162float(h3)));
    }
}

// ---------------------------------------------------------------------------
// bf16x3 NT-GEMM on mma.sync, 3-stage cp.async pipeline.
// CTA tile 128x128, warp tile 64x32 (2x4 warps), k staged 64.
// MODE 0: fp32 row-major out.  MODE 1: bf16 hi/lo split, head-major, * scale.
// ---------------------------------------------------------------------------
#define GEMM_SMEM (3 * 65536)

template <int MODE>
__global__ __launch_bounds__(256) void gemm_mma(
    const bf16* __restrict__ Ah, const bf16* __restrict__ Al,
    const bf16* __restrict__ Bh, const bf16* __restrict__ Bl,
    const float* __restrict__ bias, float* __restrict__ outF,
    bf16* __restrict__ oH, bf16* __restrict__ oL, float scale) {
    extern __shared__ char smem[];
    const uint32_t sbase = smem_u32(smem);
    const int tid = threadIdx.x;
    const int lane = tid & 31;
    const int w = tid >> 5;
    const int wm = w >> 2, wn = w & 3;
    const int bm = blockIdx.y * 128, bn = blockIdx.x * 128;

    auto load_stage = [&](int kt, int b) {
        uint32_t s0 = sbase + b * 65536;
        load_tile<128>(s0 +     0, Ah + (size_t)bm * DM + kt, DM, tid);
        load_tile<128>(s0 + 16384, Al + (size_t)bm * DM + kt, DM, tid);
        load_tile<128>(s0 + 32768, Bh + (size_t)bn * DM + kt, DM, tid);
        load_tile<128>(s0 + 49152, Bl + (size_t)bn * DM + kt, DM, tid);
        cp_commit();
    };

    float c[4][4][4];
#pragma unroll
    for (int i = 0; i < 4; i++)
#pragma unroll
        for (int j = 0; j < 4; j++)
#pragma unroll
            for (int k = 0; k < 4; k++) c[i][j][k] = 0.f;

    load_stage(0, 0);
    load_stage(64, 1);
    load_stage(128, 2);

    for (int it = 0; it < 16; it++) {
        if (it <= 13)      asm volatile("cp.async.wait_group 2;" ::: "memory");
        else if (it == 14) asm volatile("cp.async.wait_group 1;" ::: "memory");
        else               asm volatile("cp.async.wait_group 0;" ::: "memory");
        __syncthreads();

        uint32_t s0 = sbase + (it % 3) * 65536;
#pragma unroll
        for (int s = 0; s < 4; s++) {
            uint32_t aH[4][4], aL[4][4], bH[2][4], bL[2][4];
#pragma unroll
            for (int mt = 0; mt < 4; mt++) {
                ldfragA(aH[mt], s0,         wm * 64 + mt * 16, 2 * s, lane);
                ldfragA(aL[mt], s0 + 16384, wm * 64 + mt * 16, 2 * s, lane);
            }
#pragma unroll
            for (int np = 0; np < 2; np++) {
                ldfragB(bH[np], s0 + 32768, wn * 32 + np * 16, 2 * s, lane);
                ldfragB(bL[np], s0 + 49152, wn * 32 + np * 16, 2 * s, lane);
            }
#pragma unroll
            for (int mt = 0; mt < 4; mt++)
#pragma unroll
                for (int np = 0; np < 2; np++)
#pragma unroll
                    for (int hf = 0; hf < 2; hf++) {
                        int nt = np * 2 + hf;
                        mma_bf16(c[mt][nt], aH[mt], bH[np][2 * hf], bH[np][2 * hf + 1]);
                        mma_bf16(c[mt][nt], aH[mt], bL[np][2 * hf], bL[np][2 * hf + 1]);
                        mma_bf16(c[mt][nt], aL[mt], bH[np][2 * hf], bH[np][2 * hf + 1]);
                    }
        }
        __syncthreads();
        if (it + 3 < 16) load_stage((it + 3) * 64, it % 3);
    }

#pragma unroll
    for (int mt = 0; mt < 4; mt++)
#pragma unroll
        for (int nt = 0; nt < 4; nt++) {
            int r0 = bm + wm * 64 + mt * 16 + (lane >> 2);
            int col = bn + wn * 32 + nt * 8 + 2 * (lane & 3);
            float b0 = bias[col], b1 = bias[col + 1];
#pragma unroll
            for (int h2 = 0; h2 < 2; h2++) {
                int r = r0 + h2 * 8;
                float x0 = (c[mt][nt][2 * h2]     + b0) * scale;
                float x1 = (c[mt][nt][2 * h2 + 1] + b1) * scale;
                if (MODE == 0) {
                    float2 v = {x0, x1};
                    *(float2*)(outF + (size_t)r * DM + col) = v;
                } else {
                    bf16 h0 = __float2bfloat16_rn(x0);
                    bf16 h1 = __float2bfloat16_rn(x1);
                    size_t off = ((size_t)(col >> 6) * NTOK + r) * DKH + (col & 63);
                    *(bf162*)(oH + off) = bf162(h0, h1);
                    *(bf162*)(oL + off) =
                        bf162(__float2bfloat16_rn(x0 - __bfloat162float(h0)),
                              __float2bfloat16_rn(x1 - __bfloat162float(h1)));
                }
            }
        }
}

// ---------------------------------------------------------------------------
// Flash attention on mma.sync bf16x3.
// Block: (256 q rows, 1 head) = 8 warps x 32 rows. Single wave (128 CTAs).
// Smem: Qh@0 (32K), Ql@32K; kv buf b @64K + b*32K: Kh,Kl,Vh,Vl (8K each).
// ---------------------------------------------------------------------------
#define ATTN_SMEM (65536 + 2 * 32768)

__global__ __launch_bounds__(256, 1) void attn_mma() {
    extern __shared__ char smem[];
    const uint32_t sbase = smem_u32(smem);
    const int h = blockIdx.y;
    const int row0 = blockIdx.x * 256;
    const int tid = threadIdx.x;
    const int lane = tid & 31;
    const int w = tid >> 5;

    const size_t hbase = (size_t)h * NTOK * DKH;

    load_tile<256>(sbase,         g_Qh + hbase + (size_t)row0 * DKH, DKH, tid);
    load_tile<256>(sbase + 32768, g_Ql + hbase + (size_t)row0 * DKH, DKH, tid);
    cp_commit();

    auto kvb = [&](int b) { return sbase + 65536 + b * 32768; };
    auto load_kv = [&](int t, int b) {
        size_t off = hbase + (size_t)t * 64 * DKH;
        uint32_t s0 = kvb(b);
        load_tile<64>(s0 +     0, g_Kh + off, DKH, tid);
        load_tile<64>(s0 +  8192, g_Kl + off, DKH, tid);
        load_tile<64>(s0 + 16384, g_Vh + off, DKH, tid);
        load_tile<64>(s0 + 24576, g_Vl + off, DKH, tid);
        cp_commit();
    };

    load_kv(0, 0);
    load_kv(1, 1);

    float m[2][2], l[2][2];
    float o[2][8][4];
#pragma unroll
    for (int mt = 0; mt < 2; mt++) {
        m[mt][0] = m[mt][1] = -1e30f;
        l[mt][0] = l[mt][1] = 0.f;
#pragma unroll
        for (int nt = 0; nt < 8; nt++)
#pragma unroll
            for (int j = 0; j < 4; j++) o[mt][nt][j] = 0.f;
    }

    for (int i = 0; i < NTOK / 64; i++) {
        const int b = i & 1;
        if (i < NTOK / 64 - 1) asm volatile("cp.async.wait_group 1;" ::: "memory");
        else                   asm volatile("cp.async.wait_group 0;" ::: "memory");
        __syncthreads();
        const uint32_t s0 = kvb(b);

        // S = Q K^T  (1/sqrt(dk) folded into Q)
        float sc[2][8][4];
#pragma unroll
        for (int mt = 0; mt < 2; mt++)
#pragma unroll
            for (int nt = 0; nt < 8; nt++)
#pragma unroll
                for (int j = 0; j < 4; j++) sc[mt][nt][j] = 0.f;

#pragma unroll
        for (int s = 0; s < 4; s++) {
            uint32_t kh[4][4], kl[4][4], qhf[2][4], qlf[2][4];
#pragma unroll
            for (int np = 0; np < 4; np++) {
                ldfragB(kh[np], s0,        np * 16, 2 * s, lane);
                ldfragB(kl[np], s0 + 8192, np * 16, 2 * s, lane);
            }
#pragma unroll
            for (int mt = 0; mt < 2; mt++) {
                ldfragA(qhf[mt], sbase,         w * 32 + mt * 16, 2 * s, lane);
                ldfragA(qlf[mt], sbase + 32768, w * 32 + mt * 16, 2 * s, lane);
            }
#pragma unroll
            for (int mt = 0; mt < 2; mt++)
#pragma unroll
                for (int np = 0; np < 4; np++)
#pragma unroll
                    for (int hf = 0; hf < 2; hf++) {
                        int nt = np * 2 + hf;
                        mma_bf16(sc[mt][nt], qhf[mt], kh[np][2 * hf], kh[np][2 * hf + 1]);
                        mma_bf16(sc[mt][nt], qhf[mt], kl[np][2 * hf], kl[np][2 * hf + 1]);
                        mma_bf16(sc[mt][nt], qlf[mt], kh[np][2 * hf], kh[np][2 * hf + 1]);
                    }
        }

        // online softmax (per mt, per row-half h2; quad shuffles)
#pragma unroll
        for (int mt = 0; mt < 2; mt++)
#pragma unroll
            for (int h2 = 0; h2 < 2; h2++) {
                float mx = -1e30f;
#pragma unroll
                for (int nt = 0; nt < 8; nt++)
                    mx = fmaxf(mx, fmaxf(sc[mt][nt][2 * h2], sc[mt][nt][2 * h2 + 1]));
                mx = fmaxf(mx, __shfl_xor_sync(0xffffffffu, mx, 1));
                mx = fmaxf(mx, __shfl_xor_sync(0xffffffffu, mx, 2));
                float mnew = fmaxf(m[mt][h2], mx);
                float corr = exp2f((m[mt][h2] - mnew) * LOG2E);
                m[mt][h2] = mnew;
                float ls = 0.f;
#pragma unroll
                for (int nt = 0; nt < 8; nt++) {
                    float p0 = exp2f((sc[mt][nt][2 * h2]     - mnew) * LOG2E);
                    float p1 = exp2f((sc[mt][nt][2 * h2 + 1] - mnew) * LOG2E);
                    sc[mt][nt][2 * h2] = p0;
                    sc[mt][nt][2 * h2 + 1] = p1;
                    ls += p0 + p1;
                }
                ls += __shfl_xor_sync(0xffffffffu, ls, 1);
                ls += __shfl_xor_sync(0xffffffffu, ls, 2);
                l[mt][h2] = l[mt][h2] * corr + ls;
#pragma unroll
                for (int nt = 0; nt < 8; nt++) {
                    o[mt][nt][2 * h2] *= corr;
                    o[mt][nt][2 * h2 + 1] *= corr;
                }
            }

        // O += P V  (P converted to hi/lo A-fragments on the fly)
#pragma unroll
        for (int s = 0; s < 4; s++) {
            uint32_t vh[4][4], vl[4][4];
#pragma unroll
            for (int tp = 0; tp < 4; tp++) {
                ldfragV(vh[tp], s0 + 16384, s * 16, 2 * tp, lane);
                ldfragV(vl[tp], s0 + 24576, s * 16, 2 * tp, lane);
            }
#pragma unroll
            for (int mt = 0; mt < 2; mt++) {
                uint32_t pah[4], pal[4];
#pragma unroll
                for (int j = 0; j < 4; j++) {
                    int t = 2 * s + (j >> 1);
                    float v0 = sc[mt][t][(j & 1) * 2];
                    float v1 = sc[mt][t][(j & 1) * 2 + 1];
                    bf16 h0 = __float2bfloat16_rn(v0);
                    bf16 h1 = __float2bfloat16_rn(v1);
                    bf162 ph = bf162(h0, h1);
                    bf162 pl = bf162(__float2bfloat16_rn(v0 - __bfloat162float(h0)),
                                     __float2bfloat16_rn(v1 - __bfloat162float(h1)));
                    pah[j] = *(uint32_t*)&ph;
                    pal[j] = *(uint32_t*)&pl;
                }
#pragma unroll
                for (int tp = 0; tp < 4; tp++)
#pragma unroll
                    for (int hf = 0; hf < 2; hf++) {
                        int nt = tp * 2 + hf;
                        mma_bf16(o[mt][nt], pah, vh[tp][2 * hf], vh[tp][2 * hf + 1]);
                        mma_bf16(o[mt][nt], pah, vl[tp][2 * hf], vl[tp][2 * hf + 1]);
                        mma_bf16(o[mt][nt], pal, vh[tp][2 * hf], vh[tp][2 * hf + 1]);
                    }
            }
        }

        __syncthreads();
        if (i + 2 < NTOK / 64) load_kv(i + 2, b);
    }

    // Epilogue: normalize, split hi/lo, write concat layout [row][h*64+col]
#pragma unroll
    for (int mt = 0; mt < 2; mt++)
#pragma unroll
        for (int h2 = 0; h2 < 2; h2++) {
            float inv = 1.f / l[mt][h2];
            int r = row0 + w * 32 + mt * 16 + h2 * 8 + (lane >> 2);
#pragma unroll
            for (int nt = 0; nt < 8; nt++) {
                int col = nt * 8 + 2 * (lane & 3);
                float x0 = o[mt][nt][2 * h2] * inv;
                float x1 = o[mt][nt][2 * h2 + 1] * inv;
                bf16 h0 = __float2bfloat16_rn(x0);
                bf16 h1 = __float2bfloat16_rn(x1);
                size_t off = (size_t)r * DM + h * DKH + col;
                *(bf162*)(g_Ch + off) = bf162(h0, h1);
                *(bf162*)(g_Cl + off) =
                    bf162(__float2bfloat16_rn(x0 - __bfloat162float(h0)),
                          __float2bfloat16_rn(x1 - __bfloat162float(h1)));
            }
        }
}

// ---------------------------------------------------------------------------
extern "C" void kernel_launch(void* const* d_in, const int* in_sizes, int n_in,
                              void* d_out, int out_size) {
    const float* q  = (const float*)d_in[0];
    const float* k  = (const float*)d_in[1];
    const float* v  = (const float*)d_in[2];
    const float* Wq = (const float*)d_in[3];
    const float* bq = (const float*)d_in[4];
    const float* Wk = (const float*)d_in[5];
    const float* bk = (const float*)d_in[6];
    const float* Wv = (const float*)d_in[7];
    const float* bv = (const float*)d_in[8];
    const float* Wo = (const float*)d_in[9];
    const float* bo = (const float*)d_in[10];
    float* out = (float*)d_out;

    bf16 *qh, *ql, *kh, *kl, *vh, *vl;
    bf16 *Wqh, *Wql, *Wkh, *Wkl, *Wvh, *Wvl, *Woh, *Wol;
    bf16 *Qh, *Ql, *Kh, *Kl, *Vh, *Vl, *Ch, *Cl;
    cudaGetSymbolAddress((void**)&qh, g_qh);   cudaGetSymbolAddress((void**)&ql, g_ql);
    cudaGetSymbolAddress((void**)&kh, g_kh);   cudaGetSymbolAddress((void**)&kl, g_kl);
    cudaGetSymbolAddress((void**)&vh, g_vh);   cudaGetSymbolAddress((void**)&vl, g_vl);
    cudaGetSymbolAddress((void**)&Wqh, g_Wqh); cudaGetSymbolAddress((void**)&Wql, g_Wql);
    cudaGetSymbolAddress((void**)&Wkh, g_Wkh); cudaGetSymbolAddress((void**)&Wkl, g_Wkl);
    cudaGetSymbolAddress((void**)&Wvh, g_Wvh); cudaGetSymbolAddress((void**)&Wvl, g_Wvl);
    cudaGetSymbolAddress((void**)&Woh, g_Woh); cudaGetSymbolAddress((void**)&Wol, g_Wol);
    cudaGetSymbolAddress((void**)&Qh, g_Qh);   cudaGetSymbolAddress((void**)&Ql, g_Ql);
    cudaGetSymbolAddress((void**)&Kh, g_Kh);   cudaGetSymbolAddress((void**)&Kl, g_Kl);
    cudaGetSymbolAddress((void**)&Vh, g_Vh);   cudaGetSymbolAddress((void**)&Vl, g_Vl);
    cudaGetSymbolAddress((void**)&Ch, g_Ch);   cudaGetSymbolAddress((void**)&Cl, g_Cl);

    cudaFuncSetAttribute(gemm_mma<0>, cudaFuncAttributeMaxDynamicSharedMemorySize, GEMM_SMEM);
    cudaFuncSetAttribute(gemm_mma<1>, cudaFuncAttributeMaxDynamicSharedMemorySize, GEMM_SMEM);
    cudaFuncSetAttribute(attn_mma, cudaFuncAttributeMaxDynamicSharedMemorySize, ATTN_SMEM);

    const int nQKV4 = NTOK * DM / 4;   // 524288
    const int nW4 = DM * DM / 4;       // 262144

    CvtJobs jobs;
    jobs.src[0] = q;  jobs.hi[0] = qh;  jobs.lo[0] = ql;  jobs.n4[0] = nQKV4;
    jobs.src[1] = k;  jobs.hi[1] = kh;  jobs.lo[1] = kl;  jobs.n4[1] = nQKV4;
    jobs.src[2] = v;  jobs.hi[2] = vh;  jobs.lo[2] = vl;  jobs.n4[2] = nQKV4;
    jobs.src[3] = Wq; jobs.hi[3] = Wqh; jobs.lo[3] = Wql; jobs.n4[3] = nW4;
    jobs.src[4] = Wk; jobs.hi[4] = Wkh; jobs.lo[4] = Wkl; jobs.n4[4] = nW4;
    jobs.src[5] = Wv; jobs.hi[5] = Wvh; jobs.lo[5] = Wvl; jobs.n4[5] = nW4;
    jobs.src[6] = Wo; jobs.hi[6] = Woh; jobs.lo[6] = Wol; jobs.n4[6] = nW4;
    cvt_all<<<dim3(nQKV4 / 1024, 7), 256>>>(jobs);

    dim3 gg(DM / 128, NTOK / 128);  // (8,16)
    gemm_mma<1><<<gg, 256, GEMM_SMEM>>>(qh, ql, Wqh, Wql, bq, nullptr, Qh, Ql, 0.125f);
    gemm_mma<1><<<gg, 256, GEMM_SMEM>>>(kh, kl, Wkh, Wkl, bk, nullptr, Kh, Kl, 1.0f);
    gemm_mma<1><<<gg, 256, GEMM_SMEM>>>(vh, vl, Wvh, Wvl, bv, nullptr, Vh, Vl, 1.0f);

    attn_mma<<<dim3(NTOK / 256, HEADS), 256, ATTN_SMEM>>>();

    gemm_mma<0><<<gg, 256, GEMM_SMEM>>>(Ch, Cl, Woh, Wol, bo, out, nullptr, nullptr, 1.0f);
}